// round 16
// baseline (speedup 1.0000x reference)
#include <cuda_runtime.h>
#include <cuda_bf16.h>
#include <cstdint>

// ---------------------------------------------------------------------------
// Problem constants
// ---------------------------------------------------------------------------
#define NN      20000
#define TT      64
#define FF      128
#define BB      8192
#define KK      32
#define QQ      (3*BB)            // 24576
#define WWIN    64
#define QK      (QQ*KK)           // 786432
#define TILE_E  64                // edges per tile (= 2 full queries)
#define TILES2  (QK/TILE_E)       // 12288 tiles per direction
#define NTILE   8                 // tiles per block (w1 staged once)
#define EBLK    (TILES2/NTILE)    // 1536 blocks per direction

// Edge-kernel dynamic smem:
//   As2[64 k2][66 u64]  = 33792 B   (k-pair packed A, 64 edge cols + pad)
//   Bs2[64 k2][66 u64]  = 33792 B   (k-pair packed w1)
//   spart[16][64] f32   =  4096 B
//   srowS/sdeltaS[256]  =  2048 B
#define SMEM_EK (33792 + 33792 + 4096 + 2048)   // 73728 B -> occupancy 3

// Score-kernel dynamic smem (floats): s_w1[193*128] | srow[8][200]
#define SMEM_SC ((193*128 + 8*200) * 4)         // 105216 B

// ---------------------------------------------------------------------------
// Device scratch (static __device__ arrays — allocation APIs are forbidden)
// ---------------------------------------------------------------------------
__device__ int    g_flags[2];                 // [0]=not01, [1]=not0f
__device__ float  g_demb[2*65*64];            // per-dir (delta_emb@w1_delta + b1)
__device__ float  g_hsum[2*(size_t)QQ*64];    // per-(dir,query) sum of relu hidden
__device__ int    g_cnt[2*QQ];                // per-(dir,query) valid-edge count
__device__ float  g_feat[(size_t)QQ*256];     // [x_vt | m_in | m_out]
__device__ float  g_u1[(size_t)QQ*128];       // combine hidden 1
__device__ float  g_feat2[(size_t)BB*193];    // scorer features

// ---------------------------------------------------------------------------
// f32x2 helpers (sm_103a packed fp32 — 2x FFMA throughput)
// ---------------------------------------------------------------------------
__device__ __forceinline__ unsigned long long ffma2(unsigned long long a,
                                                    unsigned long long b,
                                                    unsigned long long c) {
    unsigned long long d;
    asm("fma.rn.f32x2 %0, %1, %2, %3;" : "=l"(d) : "l"(a), "l"(b), "l"(c));
    return d;
}
__device__ __forceinline__ unsigned long long pack2(float lo, float hi) {
    unsigned long long r;
    asm("mov.b64 %0, {%1, %2};" : "=l"(r) : "f"(lo), "f"(hi));
    return r;
}
__device__ __forceinline__ unsigned long long dup2(float v) {
    unsigned long long r;
    asm("mov.b64 %0, {%1, %2};" : "=l"(r) : "f"(v), "f"(v));
    return r;
}
__device__ __forceinline__ float2 unpack2(unsigned long long v) {
    float2 r;
    asm("mov.b64 {%0, %1}, %2;" : "=f"(r.x), "=f"(r.y) : "l"(v));
    return r;
}
__device__ __forceinline__ int read_mask(const void* p, int idx, int mode) {
    if (mode == 1) return ((const int*)p)[idx] != 0;
    if (mode == 2) return ((const float*)p)[idx] != 0.0f;
    return ((const unsigned char*)p)[idx] != 0;
}

// ---------------------------------------------------------------------------
// K1: flag reset (graph-safe) + delta tables (2 blocks).
// Launched BEFORE detect, so the reset is ordered ahead of all atomicOr.
// ---------------------------------------------------------------------------
__global__ void its_tables_kernel(const float* __restrict__ demb,
                                  const float* __restrict__ piw1, const float* __restrict__ pib1,
                                  const float* __restrict__ pow1, const float* __restrict__ pob1) {
    int dir = blockIdx.x;
    if (dir == 0 && threadIdx.x == 0) { g_flags[0] = 0; g_flags[1] = 0; }
    const float* w1 = dir ? pow1 : piw1;
    const float* b1 = dir ? pob1 : pib1;
    float* out = g_demb + dir * (65*64);
    for (int idx = threadIdx.x; idx < 65*64; idx += blockDim.x) {
        int d = idx >> 6, j = idx & 63;
        float acc = b1[j];
#pragma unroll
        for (int dd = 0; dd < 16; dd++)
            acc += demb[d*16 + dd] * w1[(128 + dd)*64 + j];
        out[idx] = acc;
    }
}

// ---------------------------------------------------------------------------
// K0: classify mask serialization, parallel, deterministic flags via atomicOr
// ---------------------------------------------------------------------------
__global__ void its_detect_kernel(const unsigned int* __restrict__ m) {
    int l01 = 0, l0f = 0;
    for (int i = blockIdx.x * blockDim.x + threadIdx.x; i < QK/4;
         i += gridDim.x * blockDim.x) {
        unsigned v = m[i];
        if (v > 1u) l01 = 1;
        if (v != 0u && v != 0x3F800000u) l0f = 1;
    }
    l01 = __syncthreads_or(l01);
    l0f = __syncthreads_or(l0f);
    if (threadIdx.x == 0) {
        if (l01) atomicOr(&g_flags[0], 1);
        if (l0f) atomicOr(&g_flags[1], 1);
    }
}

// ---------------------------------------------------------------------------
// K2: edge aggregation — warp-autonomous tiles + K-PAIR PACKED operands.
// As2[k2][e] / Bs2[k2][j] hold (even-k, odd-k) f32 pairs; one FFMA2 performs
// the 2-k dot step for one (e,j): no dup2 MOVs, 20-slot inner loop per 2k.
// Gather transpose uses STS.64 (16/thread instead of 32 STS.32).
// ---------------------------------------------------------------------------
__global__ void __launch_bounds__(256, 3)
its_edge_kernel(const float* __restrict__ x,
                const int* __restrict__ in_u,  const int* __restrict__ in_tau,
                const void* __restrict__ in_mask,
                const int* __restrict__ out_u, const int* __restrict__ out_tau,
                const void* __restrict__ out_mask,
                const int* __restrict__ times,
                const float* __restrict__ piw1, const float* __restrict__ pow1) {
    extern __shared__ unsigned long long smu[];
    unsigned long long* As2 = smu;                 // [64 k2][66]
    unsigned long long* Bs2 = smu + 64*66;         // [64 k2][66]
    float* spart = (float*)(smu + 2*64*66);        // [16][64]
    int* srowS   = (int*)(spart + 16*64);          // [8 warps][32]
    int* sdeltaS = srowS + 256;                    // [8 warps][32]

    int bid  = blockIdx.x;
    int dir  = (bid >= EBLK) ? 1 : 0;
    int bslot = bid - dir * EBLK;
    const int*  uu = dir ? out_u   : in_u;
    const int*  tt = dir ? out_tau : in_tau;
    const void* mm = dir ? out_mask : in_mask;
    const float* w1 = dir ? pow1 : piw1;
    const float* gdemb = g_demb + dir * 4160;
    int tid = threadIdx.x;
    int wid = tid >> 5, lane = tid & 31;
    int mode;
    {
        int f01 = g_flags[0], f0f = g_flags[1];
        mode = (!f01) ? 1 : ((!f0f) ? 2 : 0);
    }

    // Stage w1 as k-pairs ONCE per block: Bs2[k2][j] = (w1[2k2][j], w1[2k2+1][j])
    for (int i = tid; i < 1024; i += 256) {         // 64 k2 x 16 j-quads
        int k2 = i >> 4, j4 = (i & 15) * 4;
        float4 ve = *(const float4*)(w1 + (size_t)(2*k2)*64 + j4);
        float4 vo = *(const float4*)(w1 + (size_t)(2*k2 + 1)*64 + j4);
        ulonglong2 p0, p1;
        p0.x = pack2(ve.x, vo.x); p0.y = pack2(ve.y, vo.y);
        p1.x = pack2(ve.z, vo.z); p1.y = pack2(ve.w, vo.w);
        *(ulonglong2*)(Bs2 + k2*66 + j4)     = p0;
        *(ulonglong2*)(Bs2 + k2*66 + j4 + 2) = p1;
    }
    __syncthreads();

    // Warp-invariant coordinates
    int wq   = wid >> 2;                    // warp's query within tile (0/1)
    int ebq  = (wid & 3) * 8;               // warp's edge base within query
    int r0   = wid*8 + ((lane >> 4) << 2);  // As2 column base (4 edges)
    int o0   = (lane & 15) * 4;             // j base (u64 index == j index)
    int te   = wid*2 + (lane >> 4);         // spart group

    for (int it = 0; it < NTILE; it++) {
        int tile = bslot * NTILE + it;
        int q = tile*2 + wq;

        // --- per-warp metadata + compaction (4x redundant, L1-hot) ---
        int s = tile*TILE_E + wq*32 + lane;
        int t = times[q];
        int u = uu[s], ta = tt[s];
        int d = dir ? (ta - t) : (t - ta);
        d = d < 0 ? 0 : (d > WWIN ? WWIN : d);
        int mk = read_mask(mm, s, mode);
        unsigned bal = __ballot_sync(0xffffffffu, mk);
        int cnt = __popc(bal);
        int pos = __popc(bal & ((1u << lane) - 1u));
        if (mk) {
            srowS[wid*32 + pos]   = u*TT + ta;
            sdeltaS[wid*32 + pos] = d;
        }
        __syncwarp();
        if (ebq == 0 && lane == 0) g_cnt[dir*QQ + q] = cnt;

        int active = ebq < cnt;
        if (active) {
            // --- warp-local gather: k-quad -> two k-pair STS.64 rows ---
            int el = ebq + (lane >> 2);    // compacted pos in query
            int h  = lane & 3;
            int eg = wq*32 + el;           // global As2 column
            if (el < cnt) {
                int row = srowS[wid*32 + el];
                const float4* src = (const float4*)(x + (size_t)row*128);
#pragma unroll
                for (int i = 0; i < 8; i++) {
                    float4 v = src[h + i*4];          // k = 4h + 16i .. +3
                    int k2a = 2*h + 8*i;
                    As2[k2a*66 + eg]       = pack2(v.x, v.y);
                    As2[(k2a + 1)*66 + eg] = pack2(v.z, v.w);
                }
            } else {
#pragma unroll
                for (int i = 0; i < 8; i++) {
                    int k2a = 2*h + 8*i;
                    As2[k2a*66 + eg]       = 0ull;
                    As2[(k2a + 1)*66 + eg] = 0ull;
                }
            }
            __syncwarp();

            // --- FFMA2 GEMM, k-pair packed: 4 LDS + 16 FFMA2 per k2 ---
            unsigned long long acc[4][4];
#pragma unroll
            for (int e = 0; e < 4; e++)
#pragma unroll
                for (int j = 0; j < 4; j++) acc[e][j] = 0ull;

#pragma unroll 8
            for (int k2 = 0; k2 < 64; k2++) {
                const unsigned long long* ar = As2 + k2*66 + r0;
                const unsigned long long* br = Bs2 + k2*66 + o0;
                ulonglong2 aA = *(const ulonglong2*)ar;
                ulonglong2 aB = *(const ulonglong2*)(ar + 2);
                ulonglong2 b0 = *(const ulonglong2*)br;
                ulonglong2 b1 = *(const ulonglong2*)(br + 2);
                acc[0][0] = ffma2(aA.x, b0.x, acc[0][0]);
                acc[0][1] = ffma2(aA.x, b0.y, acc[0][1]);
                acc[0][2] = ffma2(aA.x, b1.x, acc[0][2]);
                acc[0][3] = ffma2(aA.x, b1.y, acc[0][3]);
                acc[1][0] = ffma2(aA.y, b0.x, acc[1][0]);
                acc[1][1] = ffma2(aA.y, b0.y, acc[1][1]);
                acc[1][2] = ffma2(aA.y, b1.x, acc[1][2]);
                acc[1][3] = ffma2(aA.y, b1.y, acc[1][3]);
                acc[2][0] = ffma2(aB.x, b0.x, acc[2][0]);
                acc[2][1] = ffma2(aB.x, b0.y, acc[2][1]);
                acc[2][2] = ffma2(aB.x, b1.x, acc[2][2]);
                acc[2][3] = ffma2(aB.x, b1.y, acc[2][3]);
                acc[3][0] = ffma2(aB.y, b0.x, acc[3][0]);
                acc[3][1] = ffma2(aB.y, b0.y, acc[3][1]);
                acc[3][2] = ffma2(aB.y, b1.x, acc[3][2]);
                acc[3][3] = ffma2(aB.y, b1.y, acc[3][3]);
            }

            // --- fold even+odd, + demb[delta], relu, masked partials ---
            float part[4] = {0.f, 0.f, 0.f, 0.f};
#pragma unroll
            for (int e = 0; e < 4; e++) {
                int eq = (r0 + e) & 31;
                if (eq < cnt) {
                    float4 dv = *(const float4*)(gdemb + sdeltaS[wid*32 + eq]*64 + o0);
                    float2 f0 = unpack2(acc[e][0]);
                    float2 f1 = unpack2(acc[e][1]);
                    float2 f2 = unpack2(acc[e][2]);
                    float2 f3 = unpack2(acc[e][3]);
                    part[0] += fmaxf(f0.x + f0.y + dv.x, 0.f);
                    part[1] += fmaxf(f1.x + f1.y + dv.y, 0.f);
                    part[2] += fmaxf(f2.x + f2.y + dv.z, 0.f);
                    part[3] += fmaxf(f3.x + f3.y + dv.w, 0.f);
                }
            }
            spart[te*64 + o0 + 0] = part[0];
            spart[te*64 + o0 + 1] = part[1];
            spart[te*64 + o0 + 2] = part[2];
            spart[te*64 + o0 + 3] = part[3];
        } else {
            spart[te*64 + o0 + 0] = 0.f;
            spart[te*64 + o0 + 1] = 0.f;
            spart[te*64 + o0 + 2] = 0.f;
            spart[te*64 + o0 + 3] = 0.f;
        }
        __syncthreads();

        // Deterministic reduce: 8 groups per query
        if (tid < 128) {
            int rq = tid >> 6, j = tid & 63;
            float sacc = 0.f;
#pragma unroll
            for (int g = 0; g < 8; g++) sacc += spart[(rq*8 + g)*64 + j];
            g_hsum[(size_t)dir*QQ*64 + (size_t)(tile*2 + rq)*64 + j] = sacc;
        }
        __syncthreads();
    }
}

// ---------------------------------------------------------------------------
// K3: per-query m_in/m_out (hsum @ w2 / cnt + b2) + x_vt gather -> g_feat[Q,256]
// ---------------------------------------------------------------------------
#define QT 24
__global__ void __launch_bounds__(256)
its_combine_a_kernel(const float* __restrict__ x,
                     const int* __restrict__ node_ids, const int* __restrict__ times,
                     const float* __restrict__ piw2, const float* __restrict__ pib2,
                     const float* __restrict__ pow2, const float* __restrict__ pob2) {
    __shared__ float s_w2[2*64*64];
    __shared__ float s_hs[2*QT*64];
    __shared__ float s_b2[2*64];
    __shared__ int   s_cnt[2*QT];

    int qb = blockIdx.x * QT;
    int tid = threadIdx.x;

    for (int i = tid; i < 4096; i += 256) {
        s_w2[i]        = piw2[i];
        s_w2[4096 + i] = pow2[i];
    }
    if (tid < 64) { s_b2[tid] = pib2[tid]; s_b2[64 + tid] = pob2[tid]; }
    for (int i = tid; i < QT*64; i += 256) {
        int qi = i >> 6, j = i & 63;
        s_hs[i]         = g_hsum[(size_t)(qb + qi)*64 + j];
        s_hs[QT*64 + i] = g_hsum[(size_t)QQ*64 + (size_t)(qb + qi)*64 + j];
    }
    if (tid < 2*QT) {
        int dir = tid >= QT, qi = tid - dir*QT;
        s_cnt[tid] = g_cnt[dir*QQ + qb + qi];
    }
    __syncthreads();

    for (int task = tid; task < 2*QT*8; task += 256) {
        int r = task >> 3, c = task & 7;
        int dir = r >= QT, qi = r - dir*QT;
        const float* hs = s_hs + dir*QT*64 + qi*64;
        const float* w2 = s_w2 + dir*4096;
        float acc[8] = {0,0,0,0,0,0,0,0};
#pragma unroll 8
        for (int k = 0; k < 64; k++) {
            float h = hs[k];
            const float* wr = w2 + k*64 + c*8;
            float4 w0 = *(const float4*)wr;
            float4 w1 = *(const float4*)(wr + 4);
            acc[0] += h*w0.x; acc[1] += h*w0.y; acc[2] += h*w0.z; acc[3] += h*w0.w;
            acc[4] += h*w1.x; acc[5] += h*w1.y; acc[6] += h*w1.z; acc[7] += h*w1.w;
        }
        int cnt = s_cnt[dir*QT + qi];
        float inv = 1.0f / (float)(cnt > 1 ? cnt : 1);
        float bsc = cnt > 0 ? 1.0f : 0.0f;
        float* dst = g_feat + (size_t)(qb + qi)*256 + 128 + dir*64 + c*8;
#pragma unroll
        for (int j = 0; j < 8; j++)
            dst[j] = acc[j]*inv + bsc * s_b2[dir*64 + c*8 + j];
    }

    for (int task = tid; task < QT*16; task += 256) {
        int qi = task >> 4, part = task & 15;
        int q = qb + qi;
        const float* src = x + (size_t)node_ids[q]*8192 + (size_t)times[q]*128 + part*8;
        float* dst = g_feat + (size_t)q*256 + part*8;
        float4 a = ((const float4*)src)[0];
        float4 b = ((const float4*)src)[1];
        ((float4*)dst)[0] = a;
        ((float4*)dst)[1] = b;
    }
}

// ---------------------------------------------------------------------------
// K4: u1 = relu(feat @ cw1 + cb1)   [Q,256]@[256,128]
// ---------------------------------------------------------------------------
__global__ void __launch_bounds__(256)
its_gemm1_kernel(const float* __restrict__ cw1, const float* __restrict__ cb1) {
    __shared__ float As[32*68];
    __shared__ float Bs[32*128];
    int qb = blockIdx.x * 64;
    int tid = threadIdx.x;
    int qg = (tid >> 4) * 4;
    int j0 = (tid & 15) * 8;

    unsigned long long acc[4][4];
#pragma unroll
    for (int a = 0; a < 4; a++)
#pragma unroll
        for (int b = 0; b < 4; b++) acc[a][b] = 0ull;

    for (int kc = 0; kc < 256; kc += 32) {
        {
            int q = tid >> 2, kq = tid & 3;
            const float* src = g_feat + (size_t)(qb + q)*256 + kc + kq*8;
            float4 v0 = ((const float4*)src)[0];
            float4 v1 = ((const float4*)src)[1];
            int k0 = kq*8;
            As[(k0+0)*68 + q] = v0.x; As[(k0+1)*68 + q] = v0.y;
            As[(k0+2)*68 + q] = v0.z; As[(k0+3)*68 + q] = v0.w;
            As[(k0+4)*68 + q] = v1.x; As[(k0+5)*68 + q] = v1.y;
            As[(k0+6)*68 + q] = v1.z; As[(k0+7)*68 + q] = v1.w;
        }
        {
            int k = tid >> 3, jb = (tid & 7) * 16;
            const float4* src = (const float4*)(cw1 + (size_t)(kc + k)*128 + jb);
            float4* dst = (float4*)(Bs + k*128 + jb);
            dst[0] = src[0]; dst[1] = src[1]; dst[2] = src[2]; dst[3] = src[3];
        }
        __syncthreads();
#pragma unroll
        for (int k = 0; k < 32; k++) {
            float4 av = *(const float4*)(As + k*68 + qg);
            ulonglong2 bA = *(const ulonglong2*)(Bs + k*128 + j0);
            ulonglong2 bB = *(const ulonglong2*)(Bs + k*128 + j0 + 4);
            unsigned long long a0 = dup2(av.x), a1 = dup2(av.y);
            unsigned long long a2 = dup2(av.z), a3 = dup2(av.w);
            acc[0][0] = ffma2(a0, bA.x, acc[0][0]); acc[0][1] = ffma2(a0, bA.y, acc[0][1]);
            acc[0][2] = ffma2(a0, bB.x, acc[0][2]); acc[0][3] = ffma2(a0, bB.y, acc[0][3]);
            acc[1][0] = ffma2(a1, bA.x, acc[1][0]); acc[1][1] = ffma2(a1, bA.y, acc[1][1]);
            acc[1][2] = ffma2(a1, bB.x, acc[1][2]); acc[1][3] = ffma2(a1, bB.y, acc[1][3]);
            acc[2][0] = ffma2(a2, bA.x, acc[2][0]); acc[2][1] = ffma2(a2, bA.y, acc[2][1]);
            acc[2][2] = ffma2(a2, bB.x, acc[2][2]); acc[2][3] = ffma2(a2, bB.y, acc[2][3]);
            acc[3][0] = ffma2(a3, bA.x, acc[3][0]); acc[3][1] = ffma2(a3, bA.y, acc[3][1]);
            acc[3][2] = ffma2(a3, bB.x, acc[3][2]); acc[3][3] = ffma2(a3, bB.y, acc[3][3]);
        }
        __syncthreads();
    }

#pragma unroll
    for (int jp = 0; jp < 4; jp++) {
        int j = j0 + jp*2;
        float b0 = cb1[j], b1 = cb1[j+1];
#pragma unroll
        for (int qi = 0; qi < 4; qi++) {
            float2 v = unpack2(acc[qi][jp]);
            float r0 = v.x + b0; r0 = r0 > 0.f ? r0 : 0.f;
            float r1 = v.y + b1; r1 = r1 > 0.f ? r1 : 0.f;
            float* dst = g_u1 + (size_t)(qb + qg + qi)*128 + j;
            dst[0] = r0; dst[1] = r1;
        }
    }
}

// ---------------------------------------------------------------------------
// K5: h = relu(u1 @ cw2 + cb2)  [Q,128]@[128,64] -> scatter into g_feat2
// ---------------------------------------------------------------------------
__global__ void __launch_bounds__(256)
its_gemm2_kernel(const float* __restrict__ cw2, const float* __restrict__ cb2) {
    __shared__ float As[32*68];
    __shared__ float Bs[32*64];
    int qb = blockIdx.x * 64;
    int tid = threadIdx.x;
    int qg = (tid >> 4) * 4;
    int j0 = (tid & 15) * 4;

    float acc[4][4];
#pragma unroll
    for (int a = 0; a < 4; a++)
#pragma unroll
        for (int b = 0; b < 4; b++) acc[a][b] = 0.f;

    for (int kc = 0; kc < 128; kc += 32) {
        {
            int q = tid >> 2, kq = tid & 3;
            const float* src = g_u1 + (size_t)(qb + q)*128 + kc + kq*8;
            float4 v0 = ((const float4*)src)[0];
            float4 v1 = ((const float4*)src)[1];
            int k0 = kq*8;
            As[(k0+0)*68 + q] = v0.x; As[(k0+1)*68 + q] = v0.y;
            As[(k0+2)*68 + q] = v0.z; As[(k0+3)*68 + q] = v0.w;
            As[(k0+4)*68 + q] = v1.x; As[(k0+5)*68 + q] = v1.y;
            As[(k0+6)*68 + q] = v1.z; As[(k0+7)*68 + q] = v1.w;
        }
        {
            int k = tid >> 3, jb = (tid & 7) * 8;
            const float4* src = (const float4*)(cw2 + (size_t)(kc + k)*64 + jb);
            float4* dst = (float4*)(Bs + k*64 + jb);
            dst[0] = src[0]; dst[1] = src[1];
        }
        __syncthreads();
#pragma unroll
        for (int k = 0; k < 32; k++) {
            float4 av = *(const float4*)(As + k*68 + qg);
            float4 bv = *(const float4*)(Bs + k*64 + j0);
            acc[0][0] += av.x*bv.x; acc[0][1] += av.x*bv.y; acc[0][2] += av.x*bv.z; acc[0][3] += av.x*bv.w;
            acc[1][0] += av.y*bv.x; acc[1][1] += av.y*bv.y; acc[1][2] += av.y*bv.z; acc[1][3] += av.y*bv.w;
            acc[2][0] += av.z*bv.x; acc[2][1] += av.z*bv.y; acc[2][2] += av.z*bv.z; acc[2][3] += av.z*bv.w;
            acc[3][0] += av.w*bv.x; acc[3][1] += av.w*bv.y; acc[3][2] += av.w*bv.z; acc[3][3] += av.w*bv.w;
        }
        __syncthreads();
    }

#pragma unroll
    for (int qi = 0; qi < 4; qi++) {
        int gq = qb + qg + qi;
        int bb = gq / 3;
        int slot = gq - bb*3;
        float* dst = g_feat2 + (size_t)bb*193 + slot*64 + j0;
#pragma unroll
        for (int j = 0; j < 4; j++) {
            float h = acc[qi][j] + cb2[j0 + j];
            dst[j] = h > 0.f ? h : 0.f;
        }
    }
}

// ---------------------------------------------------------------------------
// K6: out[b] = relu(feat2 @ sw1 + sb1) @ sw2 + sb2
// Block = 32 b; sw1 (99KB) staged ONCE per block in dynamic smem.
// ---------------------------------------------------------------------------
__global__ void __launch_bounds__(256)
its_score_kernel(const float* __restrict__ sw1, const float* __restrict__ sb1,
                 const float* __restrict__ sw2, const float* __restrict__ sb2,
                 const float* __restrict__ d_norm, float* __restrict__ out) {
    extern __shared__ float smsc[];
    float* s_w1 = smsc;              // [193*128]
    float* srow = smsc + 24704;      // [8][200]
    int tid = threadIdx.x;
    int w = tid >> 5, lane = tid & 31;

    for (int i = tid; i < 6176; i += 256)
        ((float4*)s_w1)[i] = ((const float4*)sw1)[i];
    __syncthreads();

    float4 w2v = *(const float4*)(sw2 + lane*4);
    float sbias = sb2[0];
    float b1v0 = sb1[lane*4+0], b1v1 = sb1[lane*4+1];
    float b1v2 = sb1[lane*4+2], b1v3 = sb1[lane*4+3];

#pragma unroll
    for (int sub = 0; sub < 4; sub++) {
        int b = blockIdx.x * 32 + w * 4 + sub;
        for (int k = lane; k < 192; k += 32)
            srow[w*200 + k] = g_feat2[(size_t)b*193 + k];
        if (lane == 0) srow[w*200 + 192] = d_norm[b];
        __syncwarp();

        float a0 = 0.f, a1 = 0.f, a2 = 0.f, a3 = 0.f;
        for (int k = 0; k < 193; k++) {
            float f = srow[w*200 + k];
            float4 wv = *(const float4*)(s_w1 + k*128 + lane*4);
            a0 += f*wv.x; a1 += f*wv.y; a2 += f*wv.z; a3 += f*wv.w;
        }
        float v0 = fmaxf(a0 + b1v0, 0.f);
        float v1 = fmaxf(a1 + b1v1, 0.f);
        float v2 = fmaxf(a2 + b1v2, 0.f);
        float v3 = fmaxf(a3 + b1v3, 0.f);
        float p = v0*w2v.x + v1*w2v.y + v2*w2v.z + v3*w2v.w;
#pragma unroll
        for (int off = 16; off > 0; off >>= 1)
            p += __shfl_xor_sync(0xffffffffu, p, off);
        if (lane == 0) out[b] = p + sbias;
        __syncwarp();
    }
}

// ---------------------------------------------------------------------------
// kernel_launch
// ---------------------------------------------------------------------------
extern "C" void kernel_launch(void* const* d_in, const int* in_sizes, int n_in,
                              void* d_out, int out_size) {
    const float* x       = (const float*)d_in[0];
    const float* d_norm  = (const float*)d_in[1];
    const float* demb    = (const float*)d_in[2];
    const float* piw1    = (const float*)d_in[3];
    const float* pib1    = (const float*)d_in[4];
    const float* piw2    = (const float*)d_in[5];
    const float* pib2    = (const float*)d_in[6];
    const float* pow1    = (const float*)d_in[7];
    const float* pob1    = (const float*)d_in[8];
    const float* pow2    = (const float*)d_in[9];
    const float* pob2    = (const float*)d_in[10];
    const float* cw1     = (const float*)d_in[11];
    const float* cb1     = (const float*)d_in[12];
    const float* cw2     = (const float*)d_in[13];
    const float* cb2     = (const float*)d_in[14];
    const float* sw1     = (const float*)d_in[15];
    const float* sb1     = (const float*)d_in[16];
    const float* sw2     = (const float*)d_in[17];
    const float* sb2     = (const float*)d_in[18];
    const int* node_ids  = (const int*)d_in[19];
    const int* times     = (const int*)d_in[20];
    const int* in_u      = (const int*)d_in[21];
    const int* in_tau    = (const int*)d_in[22];
    const void* in_mask  = d_in[23];
    const int* out_u     = (const int*)d_in[24];
    const int* out_tau   = (const int*)d_in[25];
    const void* out_mask = d_in[26];
    float* out = (float*)d_out;

    cudaFuncSetAttribute(its_edge_kernel,
                         cudaFuncAttributeMaxDynamicSharedMemorySize, SMEM_EK);
    cudaFuncSetAttribute(its_score_kernel,
                         cudaFuncAttributeMaxDynamicSharedMemorySize, SMEM_SC);

    its_tables_kernel<<<2, 256>>>(demb, piw1, pib1, pow1, pob1);   // + flag reset
    its_detect_kernel<<<64, 256>>>((const unsigned int*)in_mask);
    its_edge_kernel<<<2*EBLK, 256, SMEM_EK>>>(x,
        in_u, in_tau, in_mask, out_u, out_tau, out_mask, times, piw1, pow1);
    its_combine_a_kernel<<<QQ/QT, 256>>>(x, node_ids, times, piw2, pib2, pow2, pob2);
    its_gemm1_kernel<<<QQ/64, 256>>>(cw1, cb1);
    its_gemm2_kernel<<<QQ/64, 256>>>(cw2, cb2);
    its_score_kernel<<<BB/32, 256, SMEM_SC>>>(sw1, sb1, sw2, sb2, d_norm, out);
}

// round 17
// speedup vs baseline: 1.0722x; 1.0722x over previous
#include <cuda_runtime.h>
#include <cuda_bf16.h>
#include <cstdint>

// ---------------------------------------------------------------------------
// Problem constants
// ---------------------------------------------------------------------------
#define NN      20000
#define TT      64
#define FF      128
#define BB      8192
#define KK      32
#define QQ      (3*BB)            // 24576
#define WWIN    64
#define QK      (QQ*KK)           // 786432
#define TILE_E  64                // edges per tile (= 2 full queries)
#define TILES2  (QK/TILE_E)       // 12288 tiles per direction
#define NTILE   8                 // tiles per block (w1 staged once)
#define EBLK    (TILES2/NTILE)    // 1536 blocks per direction

// Edge-kernel dynamic smem: As[128][68] | Bs[128][68] | spart[16][64] f32 + srowS/sdeltaS[256] int
#define SMEM_EK ((128*68 + 128*68 + 16*64) * 4 + 512*4)   // 75776 B -> occupancy 3

// Score-kernel dynamic smem (floats): s_w1[193*128] | srow[8][200]
#define SMEM_SC ((193*128 + 8*200) * 4)                   // 105216 B

// ---------------------------------------------------------------------------
// Device scratch (static __device__ arrays — allocation APIs are forbidden)
// ---------------------------------------------------------------------------
__device__ int    g_flags[2];                 // [0]=not01, [1]=not0f
__device__ float  g_demb[2*65*64];            // per-dir (delta_emb@w1_delta + b1)
__device__ float  g_hsum[2*(size_t)QQ*64];    // per-(dir,query) sum of relu hidden
__device__ int    g_cnt[2*QQ];                // per-(dir,query) valid-edge count
__device__ float  g_feat[(size_t)QQ*256];     // [x_vt | m_in | m_out]
__device__ float  g_u1[(size_t)QQ*128];       // combine hidden 1
__device__ float  g_feat2[(size_t)BB*193];    // scorer features

// ---------------------------------------------------------------------------
// f32x2 helpers (sm_103a packed fp32 — 2x FFMA throughput)
// ---------------------------------------------------------------------------
__device__ __forceinline__ unsigned long long ffma2(unsigned long long a,
                                                    unsigned long long b,
                                                    unsigned long long c) {
    unsigned long long d;
    asm("fma.rn.f32x2 %0, %1, %2, %3;" : "=l"(d) : "l"(a), "l"(b), "l"(c));
    return d;
}
__device__ __forceinline__ unsigned long long dup2(float v) {
    unsigned long long r;
    asm("mov.b64 %0, {%1, %2};" : "=l"(r) : "f"(v), "f"(v));
    return r;
}
__device__ __forceinline__ float2 unpack2(unsigned long long v) {
    float2 r;
    asm("mov.b64 {%0, %1}, %2;" : "=f"(r.x), "=f"(r.y) : "l"(v));
    return r;
}
__device__ __forceinline__ int read_mask(const void* p, int idx, int mode) {
    if (mode == 1) return ((const int*)p)[idx] != 0;
    if (mode == 2) return ((const float*)p)[idx] != 0.0f;
    return ((const unsigned char*)p)[idx] != 0;
}

// ---------------------------------------------------------------------------
// K1: flag reset (graph-safe) + delta tables (2 blocks).
// ---------------------------------------------------------------------------
__global__ void its_tables_kernel(const float* __restrict__ demb,
                                  const float* __restrict__ piw1, const float* __restrict__ pib1,
                                  const float* __restrict__ pow1, const float* __restrict__ pob1) {
    int dir = blockIdx.x;
    if (dir == 0 && threadIdx.x == 0) { g_flags[0] = 0; g_flags[1] = 0; }
    const float* w1 = dir ? pow1 : piw1;
    const float* b1 = dir ? pob1 : pib1;
    float* out = g_demb + dir * (65*64);
    for (int idx = threadIdx.x; idx < 65*64; idx += blockDim.x) {
        int d = idx >> 6, j = idx & 63;
        float acc = b1[j];
#pragma unroll
        for (int dd = 0; dd < 16; dd++)
            acc += demb[d*16 + dd] * w1[(128 + dd)*64 + j];
        out[idx] = acc;
    }
}

// ---------------------------------------------------------------------------
// K0: classify mask serialization, parallel, deterministic flags via atomicOr
// ---------------------------------------------------------------------------
__global__ void its_detect_kernel(const unsigned int* __restrict__ m) {
    int l01 = 0, l0f = 0;
    for (int i = blockIdx.x * blockDim.x + threadIdx.x; i < QK/4;
         i += gridDim.x * blockDim.x) {
        unsigned v = m[i];
        if (v > 1u) l01 = 1;
        if (v != 0u && v != 0x3F800000u) l0f = 1;
    }
    l01 = __syncthreads_or(l01);
    l0f = __syncthreads_or(l0f);
    if (threadIdx.x == 0) {
        if (l01) atomicOr(&g_flags[0], 1);
        if (l0f) atomicOr(&g_flags[1], 1);
    }
}

// ---------------------------------------------------------------------------
// K2: edge aggregation — warp-autonomous tiles (proven R15 design) +
// cross-tile METADATA PREFETCH: the next tile's times/u/tau/mask LDGs are
// issued before this tile's gather/GEMM, so their L2/DRAM latency drains
// under compute instead of heading each tile's critical path.
// ---------------------------------------------------------------------------
__global__ void __launch_bounds__(256, 3)
its_edge_kernel(const float* __restrict__ x,
                const int* __restrict__ in_u,  const int* __restrict__ in_tau,
                const void* __restrict__ in_mask,
                const int* __restrict__ out_u, const int* __restrict__ out_tau,
                const void* __restrict__ out_mask,
                const int* __restrict__ times,
                const float* __restrict__ piw1, const float* __restrict__ pow1) {
    extern __shared__ float sm[];
    float* As    = sm;               // [128 k][68]  (64 edge slots + pad)
    float* Bs    = As + 128*68;      // [128 k][68]  (64 j + pad)
    float* spart = Bs + 128*68;      // [16 groups][64]
    int* srowS   = (int*)(spart + 16*64);  // [8 warps][32] compacted rows
    int* sdeltaS = srowS + 256;            // [8 warps][32] compacted deltas

    int bid  = blockIdx.x;
    int dir  = (bid >= EBLK) ? 1 : 0;
    int bslot = bid - dir * EBLK;
    const int*  uu = dir ? out_u   : in_u;
    const int*  tt = dir ? out_tau : in_tau;
    const void* mm = dir ? out_mask : in_mask;
    const float* w1 = dir ? pow1 : piw1;
    const float* gdemb = g_demb + dir * 4160;
    int tid = threadIdx.x;
    int wid = tid >> 5, lane = tid & 31;
    int mode;
    {
        int f01 = g_flags[0], f0f = g_flags[1];
        mode = (!f01) ? 1 : ((!f0f) ? 2 : 0);
    }

    // Stage w1 rows 0..127 ONCE per block (8192 floats)
    for (int i = tid; i < 2048; i += 256) {
        float4 v = ((const float4*)w1)[i];
        int k = i >> 4, j = (i & 15) * 4;
        *(float4*)(Bs + k*68 + j) = v;
    }

    // Warp-invariant coordinates
    int wq   = wid >> 2;                    // warp's query within tile (0/1)
    int ebq  = (wid & 3) * 8;               // warp's edge base within query
    int r0   = wid*8 + ((lane >> 4) << 2);  // As column base for GEMM
    int o0   = (lane & 15) * 4;             // j base
    int te   = wid*2 + (lane >> 4);         // spart group

    // Prefetch metadata for tile 0
    int p_t, p_u, p_ta, p_mk;
    {
        int tile0 = bslot * NTILE;
        int s0 = tile0*TILE_E + wq*32 + lane;
        p_t  = times[tile0*2 + wq];
        p_u  = uu[s0];
        p_ta = tt[s0];
        p_mk = read_mask(mm, s0, mode);
    }
    __syncthreads();   // Bs visible to all warps before first GEMM

    for (int it = 0; it < NTILE; it++) {
        int tile = bslot * NTILE + it;
        int q = tile*2 + wq;

        // --- per-warp compaction from prefetched metadata ---
        int d = dir ? (p_ta - p_t) : (p_t - p_ta);
        d = d < 0 ? 0 : (d > WWIN ? WWIN : d);
        int mk = p_mk;
        unsigned bal = __ballot_sync(0xffffffffu, mk);
        int cnt = __popc(bal);
        int pos = __popc(bal & ((1u << lane) - 1u));
        if (mk) {
            srowS[wid*32 + pos]   = p_u*TT + p_ta;
            sdeltaS[wid*32 + pos] = d;
        }
        __syncwarp();
        if (ebq == 0 && lane == 0) g_cnt[dir*QQ + q] = cnt;

        // --- prefetch NEXT tile's metadata (latency hidden under GEMM) ---
        if (it + 1 < NTILE) {
            int s1 = (tile + 1)*TILE_E + wq*32 + lane;
            p_t  = times[(tile + 1)*2 + wq];
            p_u  = uu[s1];
            p_ta = tt[s1];
            p_mk = read_mask(mm, s1, mode);
        }

        int active = ebq < cnt;
        if (active) {
            // --- warp-local gather of its 8 compacted edges ---
            int el = ebq + (lane >> 2);    // compacted pos in query
            int h  = lane & 3;
            int eg = wq*32 + el;           // global As column
            if (el < cnt) {
                int row = srowS[wid*32 + el];
                const float4* src = (const float4*)(x + (size_t)row*128) + h*8;
#pragma unroll
                for (int i = 0; i < 8; i++) {
                    float4 v = src[i];
                    int k0 = h*32 + i*4;
                    As[(k0+0)*68 + eg] = v.x;
                    As[(k0+1)*68 + eg] = v.y;
                    As[(k0+2)*68 + eg] = v.z;
                    As[(k0+3)*68 + eg] = v.w;
                }
            } else {
#pragma unroll
                for (int i = 0; i < 8; i++) {
                    int k0 = h*32 + i*4;
                    As[(k0+0)*68 + eg] = 0.0f;
                    As[(k0+1)*68 + eg] = 0.0f;
                    As[(k0+2)*68 + eg] = 0.0f;
                    As[(k0+3)*68 + eg] = 0.0f;
                }
            }
            __syncwarp();

            // --- FFMA2 GEMM over this warp's 8 edges x 64 j ---
            unsigned long long acc[2][4];
#pragma unroll
            for (int p = 0; p < 2; p++)
#pragma unroll
                for (int j = 0; j < 4; j++) acc[p][j] = 0ull;

#pragma unroll 8
            for (int k = 0; k < 128; k++) {
                ulonglong2 a = *(const ulonglong2*)(As + k*68 + r0);
                float4 bv = *(const float4*)(Bs + k*68 + o0);
                unsigned long long b0 = dup2(bv.x), b1 = dup2(bv.y);
                unsigned long long b2 = dup2(bv.z), b3 = dup2(bv.w);
                acc[0][0] = ffma2(a.x, b0, acc[0][0]);
                acc[0][1] = ffma2(a.x, b1, acc[0][1]);
                acc[0][2] = ffma2(a.x, b2, acc[0][2]);
                acc[0][3] = ffma2(a.x, b3, acc[0][3]);
                acc[1][0] = ffma2(a.y, b0, acc[1][0]);
                acc[1][1] = ffma2(a.y, b1, acc[1][1]);
                acc[1][2] = ffma2(a.y, b2, acc[1][2]);
                acc[1][3] = ffma2(a.y, b3, acc[1][3]);
            }

            // --- epilogue: + demb[delta] (L1-hot), relu, masked partials ---
            float part[4] = {0.f, 0.f, 0.f, 0.f};
#pragma unroll
            for (int p = 0; p < 2; p++) {
                int e0 = r0 + 2*p, e1 = e0 + 1;
                int q0 = e0 & 31, q1 = e1 & 31;
                int v0 = q0 < cnt, v1 = q1 < cnt;
                float2 c0 = unpack2(acc[p][0]);
                float2 c1 = unpack2(acc[p][1]);
                float2 c2 = unpack2(acc[p][2]);
                float2 c3 = unpack2(acc[p][3]);
                if (v0) {
                    float4 dv = *(const float4*)(gdemb + sdeltaS[wid*32 + q0]*64 + o0);
                    part[0] += fmaxf(c0.x + dv.x, 0.f);
                    part[1] += fmaxf(c1.x + dv.y, 0.f);
                    part[2] += fmaxf(c2.x + dv.z, 0.f);
                    part[3] += fmaxf(c3.x + dv.w, 0.f);
                }
                if (v1) {
                    float4 dv = *(const float4*)(gdemb + sdeltaS[wid*32 + q1]*64 + o0);
                    part[0] += fmaxf(c0.y + dv.x, 0.f);
                    part[1] += fmaxf(c1.y + dv.y, 0.f);
                    part[2] += fmaxf(c2.y + dv.z, 0.f);
                    part[3] += fmaxf(c3.y + dv.w, 0.f);
                }
            }
            spart[te*64 + o0 + 0] = part[0];
            spart[te*64 + o0 + 1] = part[1];
            spart[te*64 + o0 + 2] = part[2];
            spart[te*64 + o0 + 3] = part[3];
        } else {
            spart[te*64 + o0 + 0] = 0.f;
            spart[te*64 + o0 + 1] = 0.f;
            spart[te*64 + o0 + 2] = 0.f;
            spart[te*64 + o0 + 3] = 0.f;
        }
        __syncthreads();

        // Deterministic reduce: 8 groups per query
        if (tid < 128) {
            int rq = tid >> 6, j = tid & 63;
            float s = 0.f;
#pragma unroll
            for (int g = 0; g < 8; g++) s += spart[(rq*8 + g)*64 + j];
            g_hsum[(size_t)dir*QQ*64 + (size_t)(tile*2 + rq)*64 + j] = s;
        }
        __syncthreads();   // spart / scratch safe for next tile
    }
}

// ---------------------------------------------------------------------------
// K3: per-query m_in/m_out (hsum @ w2 / cnt + b2) + x_vt gather -> g_feat[Q,256]
// ---------------------------------------------------------------------------
#define QT 24
__global__ void __launch_bounds__(256)
its_combine_a_kernel(const float* __restrict__ x,
                     const int* __restrict__ node_ids, const int* __restrict__ times,
                     const float* __restrict__ piw2, const float* __restrict__ pib2,
                     const float* __restrict__ pow2, const float* __restrict__ pob2) {
    __shared__ float s_w2[2*64*64];
    __shared__ float s_hs[2*QT*64];
    __shared__ float s_b2[2*64];
    __shared__ int   s_cnt[2*QT];

    int qb = blockIdx.x * QT;
    int tid = threadIdx.x;

    for (int i = tid; i < 4096; i += 256) {
        s_w2[i]        = piw2[i];
        s_w2[4096 + i] = pow2[i];
    }
    if (tid < 64) { s_b2[tid] = pib2[tid]; s_b2[64 + tid] = pob2[tid]; }
    for (int i = tid; i < QT*64; i += 256) {
        int qi = i >> 6, j = i & 63;
        s_hs[i]         = g_hsum[(size_t)(qb + qi)*64 + j];
        s_hs[QT*64 + i] = g_hsum[(size_t)QQ*64 + (size_t)(qb + qi)*64 + j];
    }
    if (tid < 2*QT) {
        int dir = tid >= QT, qi = tid - dir*QT;
        s_cnt[tid] = g_cnt[dir*QQ + qb + qi];
    }
    __syncthreads();

    for (int task = tid; task < 2*QT*8; task += 256) {
        int r = task >> 3, c = task & 7;
        int dir = r >= QT, qi = r - dir*QT;
        const float* hs = s_hs + dir*QT*64 + qi*64;
        const float* w2 = s_w2 + dir*4096;
        float acc[8] = {0,0,0,0,0,0,0,0};
#pragma unroll 8
        for (int k = 0; k < 64; k++) {
            float h = hs[k];
            const float* wr = w2 + k*64 + c*8;
            float4 w0 = *(const float4*)wr;
            float4 w1 = *(const float4*)(wr + 4);
            acc[0] += h*w0.x; acc[1] += h*w0.y; acc[2] += h*w0.z; acc[3] += h*w0.w;
            acc[4] += h*w1.x; acc[5] += h*w1.y; acc[6] += h*w1.z; acc[7] += h*w1.w;
        }
        int cnt = s_cnt[dir*QT + qi];
        float inv = 1.0f / (float)(cnt > 1 ? cnt : 1);
        float bsc = cnt > 0 ? 1.0f : 0.0f;
        float* dst = g_feat + (size_t)(qb + qi)*256 + 128 + dir*64 + c*8;
#pragma unroll
        for (int j = 0; j < 8; j++)
            dst[j] = acc[j]*inv + bsc * s_b2[dir*64 + c*8 + j];
    }

    for (int task = tid; task < QT*16; task += 256) {
        int qi = task >> 4, part = task & 15;
        int q = qb + qi;
        const float* src = x + (size_t)node_ids[q]*8192 + (size_t)times[q]*128 + part*8;
        float* dst = g_feat + (size_t)q*256 + part*8;
        float4 a = ((const float4*)src)[0];
        float4 b = ((const float4*)src)[1];
        ((float4*)dst)[0] = a;
        ((float4*)dst)[1] = b;
    }
}

// ---------------------------------------------------------------------------
// K4: u1 = relu(feat @ cw1 + cb1)   [Q,256]@[256,128]
// ---------------------------------------------------------------------------
__global__ void __launch_bounds__(256)
its_gemm1_kernel(const float* __restrict__ cw1, const float* __restrict__ cb1) {
    __shared__ float As[32*68];
    __shared__ float Bs[32*128];
    int qb = blockIdx.x * 64;
    int tid = threadIdx.x;
    int qg = (tid >> 4) * 4;
    int j0 = (tid & 15) * 8;

    unsigned long long acc[4][4];
#pragma unroll
    for (int a = 0; a < 4; a++)
#pragma unroll
        for (int b = 0; b < 4; b++) acc[a][b] = 0ull;

    for (int kc = 0; kc < 256; kc += 32) {
        {
            int q = tid >> 2, kq = tid & 3;
            const float* src = g_feat + (size_t)(qb + q)*256 + kc + kq*8;
            float4 v0 = ((const float4*)src)[0];
            float4 v1 = ((const float4*)src)[1];
            int k0 = kq*8;
            As[(k0+0)*68 + q] = v0.x; As[(k0+1)*68 + q] = v0.y;
            As[(k0+2)*68 + q] = v0.z; As[(k0+3)*68 + q] = v0.w;
            As[(k0+4)*68 + q] = v1.x; As[(k0+5)*68 + q] = v1.y;
            As[(k0+6)*68 + q] = v1.z; As[(k0+7)*68 + q] = v1.w;
        }
        {
            int k = tid >> 3, jb = (tid & 7) * 16;
            const float4* src = (const float4*)(cw1 + (size_t)(kc + k)*128 + jb);
            float4* dst = (float4*)(Bs + k*128 + jb);
            dst[0] = src[0]; dst[1] = src[1]; dst[2] = src[2]; dst[3] = src[3];
        }
        __syncthreads();
#pragma unroll
        for (int k = 0; k < 32; k++) {
            float4 av = *(const float4*)(As + k*68 + qg);
            ulonglong2 bA = *(const ulonglong2*)(Bs + k*128 + j0);
            ulonglong2 bB = *(const ulonglong2*)(Bs + k*128 + j0 + 4);
            unsigned long long a0 = dup2(av.x), a1 = dup2(av.y);
            unsigned long long a2 = dup2(av.z), a3 = dup2(av.w);
            acc[0][0] = ffma2(a0, bA.x, acc[0][0]); acc[0][1] = ffma2(a0, bA.y, acc[0][1]);
            acc[0][2] = ffma2(a0, bB.x, acc[0][2]); acc[0][3] = ffma2(a0, bB.y, acc[0][3]);
            acc[1][0] = ffma2(a1, bA.x, acc[1][0]); acc[1][1] = ffma2(a1, bA.y, acc[1][1]);
            acc[1][2] = ffma2(a1, bB.x, acc[1][2]); acc[1][3] = ffma2(a1, bB.y, acc[1][3]);
            acc[2][0] = ffma2(a2, bA.x, acc[2][0]); acc[2][1] = ffma2(a2, bA.y, acc[2][1]);
            acc[2][2] = ffma2(a2, bB.x, acc[2][2]); acc[2][3] = ffma2(a2, bB.y, acc[2][3]);
            acc[3][0] = ffma2(a3, bA.x, acc[3][0]); acc[3][1] = ffma2(a3, bA.y, acc[3][1]);
            acc[3][2] = ffma2(a3, bB.x, acc[3][2]); acc[3][3] = ffma2(a3, bB.y, acc[3][3]);
        }
        __syncthreads();
    }

#pragma unroll
    for (int jp = 0; jp < 4; jp++) {
        int j = j0 + jp*2;
        float b0 = cb1[j], b1 = cb1[j+1];
#pragma unroll
        for (int qi = 0; qi < 4; qi++) {
            float2 v = unpack2(acc[qi][jp]);
            float r0 = v.x + b0; r0 = r0 > 0.f ? r0 : 0.f;
            float r1 = v.y + b1; r1 = r1 > 0.f ? r1 : 0.f;
            float* dst = g_u1 + (size_t)(qb + qg + qi)*128 + j;
            dst[0] = r0; dst[1] = r1;
        }
    }
}

// ---------------------------------------------------------------------------
// K5: h = relu(u1 @ cw2 + cb2)  [Q,128]@[128,64] -> scatter into g_feat2
// ---------------------------------------------------------------------------
__global__ void __launch_bounds__(256)
its_gemm2_kernel(const float* __restrict__ cw2, const float* __restrict__ cb2) {
    __shared__ float As[32*68];
    __shared__ float Bs[32*64];
    int qb = blockIdx.x * 64;
    int tid = threadIdx.x;
    int qg = (tid >> 4) * 4;
    int j0 = (tid & 15) * 4;

    float acc[4][4];
#pragma unroll
    for (int a = 0; a < 4; a++)
#pragma unroll
        for (int b = 0; b < 4; b++) acc[a][b] = 0.f;

    for (int kc = 0; kc < 128; kc += 32) {
        {
            int q = tid >> 2, kq = tid & 3;
            const float* src = g_u1 + (size_t)(qb + q)*128 + kc + kq*8;
            float4 v0 = ((const float4*)src)[0];
            float4 v1 = ((const float4*)src)[1];
            int k0 = kq*8;
            As[(k0+0)*68 + q] = v0.x; As[(k0+1)*68 + q] = v0.y;
            As[(k0+2)*68 + q] = v0.z; As[(k0+3)*68 + q] = v0.w;
            As[(k0+4)*68 + q] = v1.x; As[(k0+5)*68 + q] = v1.y;
            As[(k0+6)*68 + q] = v1.z; As[(k0+7)*68 + q] = v1.w;
        }
        {
            int k = tid >> 3, jb = (tid & 7) * 8;
            const float4* src = (const float4*)(cw2 + (size_t)(kc + k)*64 + jb);
            float4* dst = (float4*)(Bs + k*64 + jb);
            dst[0] = src[0]; dst[1] = src[1];
        }
        __syncthreads();
#pragma unroll
        for (int k = 0; k < 32; k++) {
            float4 av = *(const float4*)(As + k*68 + qg);
            float4 bv = *(const float4*)(Bs + k*64 + j0);
            acc[0][0] += av.x*bv.x; acc[0][1] += av.x*bv.y; acc[0][2] += av.x*bv.z; acc[0][3] += av.x*bv.w;
            acc[1][0] += av.y*bv.x; acc[1][1] += av.y*bv.y; acc[1][2] += av.y*bv.z; acc[1][3] += av.y*bv.w;
            acc[2][0] += av.z*bv.x; acc[2][1] += av.z*bv.y; acc[2][2] += av.z*bv.z; acc[2][3] += av.z*bv.w;
            acc[3][0] += av.w*bv.x; acc[3][1] += av.w*bv.y; acc[3][2] += av.w*bv.z; acc[3][3] += av.w*bv.w;
        }
        __syncthreads();
    }

#pragma unroll
    for (int qi = 0; qi < 4; qi++) {
        int gq = qb + qg + qi;
        int bb = gq / 3;
        int slot = gq - bb*3;
        float* dst = g_feat2 + (size_t)bb*193 + slot*64 + j0;
#pragma unroll
        for (int j = 0; j < 4; j++) {
            float h = acc[qi][j] + cb2[j0 + j];
            dst[j] = h > 0.f ? h : 0.f;
        }
    }
}

// ---------------------------------------------------------------------------
// K6: out[b] = relu(feat2 @ sw1 + sb1) @ sw2 + sb2
// Block = 32 b; sw1 (99KB) staged ONCE per block in dynamic smem.
// ---------------------------------------------------------------------------
__global__ void __launch_bounds__(256)
its_score_kernel(const float* __restrict__ sw1, const float* __restrict__ sb1,
                 const float* __restrict__ sw2, const float* __restrict__ sb2,
                 const float* __restrict__ d_norm, float* __restrict__ out) {
    extern __shared__ float smsc[];
    float* s_w1 = smsc;              // [193*128]
    float* srow = smsc + 24704;      // [8][200]
    int tid = threadIdx.x;
    int w = tid >> 5, lane = tid & 31;

    for (int i = tid; i < 6176; i += 256)
        ((float4*)s_w1)[i] = ((const float4*)sw1)[i];
    __syncthreads();

    float4 w2v = *(const float4*)(sw2 + lane*4);
    float sbias = sb2[0];
    float b1v0 = sb1[lane*4+0], b1v1 = sb1[lane*4+1];
    float b1v2 = sb1[lane*4+2], b1v3 = sb1[lane*4+3];

#pragma unroll
    for (int sub = 0; sub < 4; sub++) {
        int b = blockIdx.x * 32 + w * 4 + sub;
        for (int k = lane; k < 192; k += 32)
            srow[w*200 + k] = g_feat2[(size_t)b*193 + k];
        if (lane == 0) srow[w*200 + 192] = d_norm[b];
        __syncwarp();

        float a0 = 0.f, a1 = 0.f, a2 = 0.f, a3 = 0.f;
        for (int k = 0; k < 193; k++) {
            float f = srow[w*200 + k];
            float4 wv = *(const float4*)(s_w1 + k*128 + lane*4);
            a0 += f*wv.x; a1 += f*wv.y; a2 += f*wv.z; a3 += f*wv.w;
        }
        float v0 = fmaxf(a0 + b1v0, 0.f);
        float v1 = fmaxf(a1 + b1v1, 0.f);
        float v2 = fmaxf(a2 + b1v2, 0.f);
        float v3 = fmaxf(a3 + b1v3, 0.f);
        float p = v0*w2v.x + v1*w2v.y + v2*w2v.z + v3*w2v.w;
#pragma unroll
        for (int off = 16; off > 0; off >>= 1)
            p += __shfl_xor_sync(0xffffffffu, p, off);
        if (lane == 0) out[b] = p + sbias;
        __syncwarp();
    }
}

// ---------------------------------------------------------------------------
// kernel_launch
// ---------------------------------------------------------------------------
extern "C" void kernel_launch(void* const* d_in, const int* in_sizes, int n_in,
                              void* d_out, int out_size) {
    const float* x       = (const float*)d_in[0];
    const float* d_norm  = (const float*)d_in[1];
    const float* demb    = (const float*)d_in[2];
    const float* piw1    = (const float*)d_in[3];
    const float* pib1    = (const float*)d_in[4];
    const float* piw2    = (const float*)d_in[5];
    const float* pib2    = (const float*)d_in[6];
    const float* pow1    = (const float*)d_in[7];
    const float* pob1    = (const float*)d_in[8];
    const float* pow2    = (const float*)d_in[9];
    const float* pob2    = (const float*)d_in[10];
    const float* cw1     = (const float*)d_in[11];
    const float* cb1     = (const float*)d_in[12];
    const float* cw2     = (const float*)d_in[13];
    const float* cb2     = (const float*)d_in[14];
    const float* sw1     = (const float*)d_in[15];
    const float* sb1     = (const float*)d_in[16];
    const float* sw2     = (const float*)d_in[17];
    const float* sb2     = (const float*)d_in[18];
    const int* node_ids  = (const int*)d_in[19];
    const int* times     = (const int*)d_in[20];
    const int* in_u      = (const int*)d_in[21];
    const int* in_tau    = (const int*)d_in[22];
    const void* in_mask  = d_in[23];
    const int* out_u     = (const int*)d_in[24];
    const int* out_tau   = (const int*)d_in[25];
    const void* out_mask = d_in[26];
    float* out = (float*)d_out;

    cudaFuncSetAttribute(its_edge_kernel,
                         cudaFuncAttributeMaxDynamicSharedMemorySize, SMEM_EK);
    cudaFuncSetAttribute(its_score_kernel,
                         cudaFuncAttributeMaxDynamicSharedMemorySize, SMEM_SC);

    its_tables_kernel<<<2, 256>>>(demb, piw1, pib1, pow1, pob1);   // + flag reset
    its_detect_kernel<<<64, 256>>>((const unsigned int*)in_mask);
    its_edge_kernel<<<2*EBLK, 256, SMEM_EK>>>(x,
        in_u, in_tau, in_mask, out_u, out_tau, out_mask, times, piw1, pow1);
    its_combine_a_kernel<<<QQ/QT, 256>>>(x, node_ids, times, piw2, pib2, pow2, pob2);
    its_gemm1_kernel<<<QQ/64, 256>>>(cw1, cb1);
    its_gemm2_kernel<<<QQ/64, 256>>>(cw2, cb2);
    its_score_kernel<<<BB/32, 256, SMEM_SC>>>(sw1, sb1, sw2, sb2, d_norm, out);
}